// round 2
// baseline (speedup 1.0000x reference)
#include <cuda_runtime.h>
#include <math.h>
#include <float.h>

#define DIN   784
#define DH    512
#define DOUT  10
#define BATCH 256

#define BM 64
#define BN 64
#define BK 16
#define KSPLIT 4
#define KCH (DIN / KSPLIT)   // 196

#define KLA_N (49 * 32)      // k0t partials
#define KLB_N 256            // k0 partials

// ---------------- device scratch (no allocations allowed) ----------------
__device__ __align__(16) float g_Ws1t[DIN * DH];          // softplus(w_sigma1) transposed [k][h]
__device__ __align__(16) float g_pmu[KSPLIT * BATCH * DH];
__device__ __align__(16) float g_pq [KSPLIT * BATCH * DH];
__device__ __align__(16) float g_m2 [BATCH * DH];
__device__ __align__(16) float g_s2 [BATCH * DH];
__device__ __align__(16) float g_Ws2[DOUT * DH];          // softplus(w_sigma2) [o][h]
__device__ __align__(16) float g_w2t[DOUT * DH];          // w_mu2 transposed [o][h]
__device__ float g_spb1[DH];
__device__ float g_spb2[DOUT];
__device__ float g_klpartA[KLA_N];
__device__ float g_klpartB[KLB_N];

// ---------------- packed f32x2 helpers ----------------
__device__ __forceinline__ unsigned long long pack2(float x, float y) {
    unsigned long long r;
    asm("mov.b64 %0, {%1, %2};" : "=l"(r) : "f"(x), "f"(y));
    return r;
}
__device__ __forceinline__ unsigned long long mul2(unsigned long long a, unsigned long long b) {
    unsigned long long r;
    asm("mul.rn.f32x2 %0, %1, %2;" : "=l"(r) : "l"(a), "l"(b));
    return r;
}
__device__ __forceinline__ unsigned long long fma2(unsigned long long a, unsigned long long b,
                                                   unsigned long long c) {
    unsigned long long r;
    asm("fma.rn.f32x2 %0, %1, %2, %3;" : "=l"(r) : "l"(a), "l"(b), "l"(c));
    return r;
}

// ---------------- softplus: fast poly for x < -1, exact fallback ----------------
// sp  = log(1+e^x) = u*P(u),  u=e^x,  P = 1 - u/2 + u^2/3 - ... + u^6/7
// lsp = log(sp)    = x + log1p(P-1)
__device__ __forceinline__ float sp_pair(float x, float& lsp) {
    if (x < -1.0f) {
        float u = __expf(x);
        float P = 1.0f + u * (-0.5f + u * (0.33333334f + u * (-0.25f +
                  u * (0.2f + u * (-0.16666667f + u * 0.14285715f)))));
        float d = P - 1.0f;
        float lp = d * (1.0f + d * (-0.5f + d * (0.33333334f + d * (-0.25f))));
        lsp = x + lp;
        return u * P;
    } else {
        float sp = logf(1.0f + expf(x));
        lsp = logf(sp);
        return sp;
    }
}
__device__ __forceinline__ float sp_only(float x) {
    if (x < -1.0f) {
        float u = __expf(x);
        float P = 1.0f + u * (-0.5f + u * (0.33333334f + u * (-0.25f +
                  u * (0.2f + u * (-0.16666667f + u * 0.14285715f)))));
        return u * P;
    }
    return logf(1.0f + expf(x));
}

// ---------------- K0t: softplus(w_sigma1) once, transposed + KL partials ----------------
// grid (49, 32), block 256 (16x16 tile)
__global__ __launch_bounds__(256) void k0t_prep(const float* __restrict__ w_sigma1) {
    __shared__ float tile[16][17];
    __shared__ float red[8];
    const int tx = threadIdx.x & 15, ty = threadIdx.x >> 4;
    const int k = blockIdx.x * 16 + tx;
    const int h = blockIdx.y * 16 + ty;

    float lsp;
    float sp = sp_pair(w_sigma1[h * DIN + k], lsp);
    tile[ty][tx] = sp;
    float acc = sp - lsp;

    #pragma unroll
    for (int s = 16; s; s >>= 1) acc += __shfl_xor_sync(0xffffffffu, acc, s);
    int warp = threadIdx.x >> 5, lane = threadIdx.x & 31;
    if (lane == 0) red[warp] = acc;
    __syncthreads();

    // transposed write: element (k', h') with k' = bx*16+ty, h' = by*16+tx
    g_Ws1t[(blockIdx.x * 16 + ty) * DH + blockIdx.y * 16 + tx] = tile[tx][ty];

    if (threadIdx.x == 0) {
        float t = 0.f;
        #pragma unroll
        for (int w = 0; w < 8; w++) t += red[w];
        g_klpartA[blockIdx.y * 49 + blockIdx.x] = t;
    }
}

// ---------------- K0: layer-2 prep + remaining KL partials ----------------
__global__ __launch_bounds__(256) void k0_prep(const float* __restrict__ w_mu1,
                                               const float* __restrict__ b_sigma1,
                                               const float* __restrict__ w_mu2,
                                               const float* __restrict__ w_sigma2,
                                               const float* __restrict__ b_sigma2) {
    const int T = gridDim.x * blockDim.x;
    const int gtid = blockIdx.x * blockDim.x + threadIdx.x;
    float acc = 0.f;
    for (int i = gtid; i < DIN * DH; i += T) {
        float v = w_mu1[i];
        acc += v * v;
    }
    for (int i = gtid; i < DOUT * DH; i += T) {
        float lsp;
        float sp = sp_pair(w_sigma2[i], lsp);
        g_Ws2[i] = sp;
        acc += sp - lsp;
    }
    for (int i = gtid; i < DH * DOUT; i += T) {
        float v = w_mu2[i];
        acc += v * v;
        g_w2t[(i % DOUT) * DH + (i / DOUT)] = v;
    }
    if (gtid < DH)   g_spb1[gtid] = sp_only(b_sigma1[gtid]);
    if (gtid < DOUT) g_spb2[gtid] = sp_only(b_sigma2[gtid]);

    __shared__ float red[8];
    #pragma unroll
    for (int s = 16; s; s >>= 1) acc += __shfl_xor_sync(0xffffffffu, acc, s);
    int warp = threadIdx.x >> 5, lane = threadIdx.x & 31;
    if (lane == 0) red[warp] = acc;
    __syncthreads();
    if (threadIdx.x == 0) {
        float t = 0.f;
        #pragma unroll
        for (int w = 0; w < 8; w++) t += red[w];
        g_klpartB[blockIdx.x] = t;
    }
}

// ---------------- K1: layer-1 dual GEMM (mu1 + quad1), split-K, packed f32x2 ----------------
__global__ __launch_bounds__(256) void k1_gemm(const float* __restrict__ x,
                                               const float* __restrict__ w_mu1) {
    __shared__ __align__(16) float As [BK][68];   // [k][b]
    __shared__ __align__(16) float B1s[BK][68];   // [k][h]
    __shared__ __align__(16) float B2s[BK][68];   // [k][h]

    const int n0 = blockIdx.x * BN;
    const int b0 = blockIdx.y * BM;
    const int ks = blockIdx.z;
    const int kstart = ks * KCH;
    const int kend   = kstart + KCH;

    const int tid = threadIdx.x;
    const int tx = tid & 15, ty = tid >> 4;   // compute microtile coords
    const int ar = tid >> 2, ac = tid & 3;    // A load coords
    const int bk = tid >> 4, bn = tid & 15;   // B load coords

    unsigned long long amu[4][2], aq[4][2];
    #pragma unroll
    for (int i = 0; i < 4; i++) {
        amu[i][0] = 0ull; amu[i][1] = 0ull;
        aq [i][0] = 0ull; aq [i][1] = 0ull;
    }

    for (int k0 = kstart; k0 < kend; k0 += BK) {
        {   // A tile transpose into [k][b]
            int k = k0 + ac * 4;
            float4 v = make_float4(0.f, 0.f, 0.f, 0.f);
            if (k < kend) v = *(const float4*)&x[(b0 + ar) * DIN + k];
            As[ac * 4 + 0][ar] = v.x;
            As[ac * 4 + 1][ar] = v.y;
            As[ac * 4 + 2][ar] = v.z;
            As[ac * 4 + 3][ar] = v.w;
        }
        {   // B1: w_mu1 [k][h]
            int k = k0 + bk;
            float4 v = make_float4(0.f, 0.f, 0.f, 0.f);
            if (k < kend) v = *(const float4*)&w_mu1[k * DH + n0 + bn * 4];
            *(float4*)&B1s[bk][bn * 4] = v;
        }
        {   // B2: precomputed softplus, already [k][h]
            int k = k0 + bk;
            float4 v = make_float4(0.f, 0.f, 0.f, 0.f);
            if (k < kend) v = *(const float4*)&g_Ws1t[k * DH + n0 + bn * 4];
            *(float4*)&B2s[bk][bn * 4] = v;
        }
        __syncthreads();

        #pragma unroll
        for (int kk = 0; kk < BK; kk++) {
            float4 a = *(const float4*)&As[kk][ty * 4];
            ulonglong2 b1 = *(const ulonglong2*)&B1s[kk][tx * 4];
            ulonglong2 b2 = *(const ulonglong2*)&B2s[kk][tx * 4];
            float av[4] = {a.x, a.y, a.z, a.w};
            #pragma unroll
            for (int i = 0; i < 4; i++) {
                unsigned long long ap  = pack2(av[i], av[i]);
                unsigned long long a2p = mul2(ap, ap);
                amu[i][0] = fma2(ap,  b1.x, amu[i][0]);
                amu[i][1] = fma2(ap,  b1.y, amu[i][1]);
                aq [i][0] = fma2(a2p, b2.x, aq [i][0]);
                aq [i][1] = fma2(a2p, b2.y, aq [i][1]);
            }
        }
        __syncthreads();
    }

    #pragma unroll
    for (int i = 0; i < 4; i++) {
        int b = b0 + ty * 4 + i;
        ulonglong2 m; m.x = amu[i][0]; m.y = amu[i][1];
        ulonglong2 q; q.x = aq [i][0]; q.y = aq [i][1];
        *(ulonglong2*)&g_pmu[(ks * BATCH + b) * DH + n0 + tx * 4] = m;
        *(ulonglong2*)&g_pq [(ks * BATCH + b) * DH + n0 + tx * 4] = q;
    }
}

// ---------------- K1b: combine split-K partials + bias + ReLU epilogue ----------------
__global__ void k1b_combine(const float* __restrict__ b_mu1) {
    const int S = BATCH * DH;
    int i4 = blockIdx.x * blockDim.x + threadIdx.x;
    int base = i4 * 4;
    if (base >= S) return;
    int h = base & (DH - 1);

    float4 m0 = *(const float4*)&g_pmu[0 * S + base];
    float4 m1 = *(const float4*)&g_pmu[1 * S + base];
    float4 m2 = *(const float4*)&g_pmu[2 * S + base];
    float4 m3 = *(const float4*)&g_pmu[3 * S + base];
    float4 q0 = *(const float4*)&g_pq [0 * S + base];
    float4 q1 = *(const float4*)&g_pq [1 * S + base];
    float4 q2 = *(const float4*)&g_pq [2 * S + base];
    float4 q3 = *(const float4*)&g_pq [3 * S + base];

    float mu[4] = {((m0.x + m1.x) + m2.x) + m3.x,
                   ((m0.y + m1.y) + m2.y) + m3.y,
                   ((m0.z + m1.z) + m2.z) + m3.z,
                   ((m0.w + m1.w) + m2.w) + m3.w};
    float qq[4] = {((q0.x + q1.x) + q2.x) + q3.x,
                   ((q0.y + q1.y) + q2.y) + q3.y,
                   ((q0.z + q1.z) + q2.z) + q3.z,
                   ((q0.w + q1.w) + q2.w) + q3.w};

    float4 om, os;
    float* pm = (float*)&om;
    float* pq = (float*)&os;
    #pragma unroll
    for (int j = 0; j < 4; j++) {
        float m = mu[j] + b_mu1[h + j];
        bool g = (m > 0.f);
        pm[j] = g ? m : 0.f;
        pq[j] = g ? (qq[j] + g_spb1[h + j]) : 0.f;
    }
    *(float4*)&g_m2[base] = om;
    *(float4*)&g_s2[base] = os;
}

// ---------------- K2: layer 2 + softmax + sandwich, ONE WARP PER BATCH ----------------
// block = 64 threads (2 warps = 2 batches), grid = 128
#define TRI_N 55
__global__ __launch_bounds__(64) void k2_layer2(const float* __restrict__ b_mu2,
                                                float* __restrict__ out) {
    // per-warp scratch: sig[0..99], t1[100..199], p[200..209], mus[210..219],
    //                   qv[220..229], rr[230..239]
    __shared__ float sh[2][240];
    const int warp = threadIdx.x >> 5, lane = threadIdx.x & 31;
    const int b = blockIdx.x * 2 + warp;
    float* S = sh[warp];

    float mid[TRI_N], amu[DOUT], aq[DOUT];
    #pragma unroll
    for (int e = 0; e < TRI_N; e++) mid[e] = 0.f;
    #pragma unroll
    for (int o = 0; o < DOUT; o++) { amu[o] = 0.f; aq[o] = 0.f; }

    const float* m2p = g_m2 + b * DH;
    const float* s2p = g_s2 + b * DH;

    #pragma unroll 4
    for (int t = 0; t < DH / 32; t++) {
        int h = t * 32 + lane;
        float m = __ldg(m2p + h);
        float s = __ldg(s2p + h);
        float mm = m * m;
        float w[DOUT], sw[DOUT];
        #pragma unroll
        for (int o = 0; o < DOUT; o++) w[o] = __ldg(&g_w2t[o * DH + h]);
        #pragma unroll
        for (int o = 0; o < DOUT; o++) {
            amu[o] += w[o] * m;
            aq [o] += __ldg(&g_Ws2[o * DH + h]) * mm;
            sw [o]  = s * w[o];
        }
        int e = 0;
        #pragma unroll
        for (int o = 0; o < DOUT; o++)
            #pragma unroll
            for (int p = o; p < DOUT; p++)
                mid[e++] += w[o] * sw[p];
    }

    // butterfly reduce all 75 accumulators across the warp
    #pragma unroll
    for (int s = 16; s; s >>= 1) {
        #pragma unroll
        for (int e = 0; e < TRI_N; e++) mid[e] += __shfl_xor_sync(0xffffffffu, mid[e], s);
        #pragma unroll
        for (int o = 0; o < DOUT; o++) {
            amu[o] += __shfl_xor_sync(0xffffffffu, amu[o], s);
            aq [o] += __shfl_xor_sync(0xffffffffu, aq [o], s);
        }
    }

    // assemble sigma3 into shared (entries distributed across lanes, static indices)
    {
        int e = 0;
        #pragma unroll
        for (int o = 0; o < DOUT; o++) {
            #pragma unroll
            for (int p = o; p < DOUT; p++) {
                if (lane == (e & 31)) {
                    float v = mid[e];
                    if (o == p) {
                        // faithful replication of reference's flattened-view trace term
                        int n  = DOUT * b + o;
                        int qn = n >> 8;
                        int mn = n & 255;
                        float trf = g_Ws2[qn * DH + 2 * mn]     * g_s2[mn * DH + mn]
                                  + g_Ws2[qn * DH + 2 * mn + 1] * g_s2[mn * DH + 256 + mn];
                        v += trf + aq[o] + g_spb2[o];
                        S[o * DOUT + o] = v;
                        S[210 + o] = amu[o] + b_mu2[o];
                    } else {
                        S[o * DOUT + p] = v;
                        S[p * DOUT + o] = v;
                    }
                }
                e++;
            }
        }
    }
    __syncwarp();

    // softmax over DOUT (whole warp, padded with -inf)
    {
        float v = (lane < DOUT) ? S[210 + lane] : -FLT_MAX;
        float mx = v;
        #pragma unroll
        for (int s = 16; s; s >>= 1) mx = fmaxf(mx, __shfl_xor_sync(0xffffffffu, mx, s));
        float e = (lane < DOUT) ? expf(v - mx) : 0.f;
        float sm = e;
        #pragma unroll
        for (int s = 16; s; s >>= 1) sm += __shfl_xor_sync(0xffffffffu, sm, s);
        if (lane < DOUT) {
            float p = e / sm;
            S[200 + lane] = p;
            out[b * DOUT + lane] = p;
        }
    }
    __syncwarp();

    // qv[k] = sum_j p[j] * sig[j][k]
    if (lane < DOUT) {
        float a = 0.f;
        #pragma unroll
        for (int j = 0; j < DOUT; j++) a += S[200 + j] * S[j * DOUT + lane];
        S[220 + lane] = a;
    }
    __syncwarp();

    // t1[i][k] = p[i] * (sig[i][k] - qv[k])
    for (int e = lane; e < DOUT * DOUT; e += 32) {
        int i = e / DOUT, k = e % DOUT;
        S[100 + e] = S[200 + i] * (S[e] - S[220 + k]);
    }
    __syncwarp();

    // rr[i] = sum_k t1[i][k] * p[k]
    if (lane < DOUT) {
        float a = 0.f;
        #pragma unroll
        for (int k = 0; k < DOUT; k++) a += S[100 + lane * DOUT + k] * S[200 + k];
        S[230 + lane] = a;
    }
    __syncwarp();

    // Sigma_out[i][l] = p[l] * (t1[i][l] - rr[i])
    for (int e = lane; e < DOUT * DOUT; e += 32) {
        int i = e / DOUT, l = e % DOUT;
        out[BATCH * DOUT + b * DOUT * DOUT + e] = S[200 + l] * (S[100 + e] - S[230 + i]);
    }
}

// ---------------- K3: KL finalize ----------------
__global__ void k3_kl(float* __restrict__ out) {
    __shared__ float s[256];
    float a = 0.f;
    for (int i = threadIdx.x; i < KLA_N; i += 256) a += g_klpartA[i];
    a += g_klpartB[threadIdx.x];
    s[threadIdx.x] = a;
    __syncthreads();
    for (int off = 128; off; off >>= 1) {
        if (threadIdx.x < off) s[threadIdx.x] += s[threadIdx.x + off];
        __syncthreads();
    }
    if (threadIdx.x == 0)
        out[BATCH * DOUT + BATCH * DOUT * DOUT] =
            0.5f * (s[0] - (float)(DH * DIN + DOUT * DH));
}

// ---------------- launch ----------------
extern "C" void kernel_launch(void* const* d_in, const int* in_sizes, int n_in,
                              void* d_out, int out_size) {
    const float* x        = (const float*)d_in[0];
    const float* w_mu1    = (const float*)d_in[1];
    const float* w_sigma1 = (const float*)d_in[2];
    const float* b_mu1    = (const float*)d_in[3];
    const float* b_sigma1 = (const float*)d_in[4];
    const float* w_mu2    = (const float*)d_in[5];
    const float* w_sigma2 = (const float*)d_in[6];
    const float* b_mu2    = (const float*)d_in[7];
    const float* b_sigma2 = (const float*)d_in[8];
    float* out = (float*)d_out;

    dim3 g0t(49, 32);
    k0t_prep<<<g0t, 256>>>(w_sigma1);
    k0_prep<<<KLB_N, 256>>>(w_mu1, b_sigma1, w_mu2, w_sigma2, b_sigma2);
    dim3 g1(DH / BN, BATCH / BM, KSPLIT);
    k1_gemm<<<g1, 256>>>(x, w_mu1);
    k1b_combine<<<(BATCH * DH / 4 + 255) / 256, 256>>>(b_mu1);
    k2_layer2<<<BATCH / 2, 64>>>(b_mu2, out);
    k3_kl<<<1, 256>>>(out);
}

// round 3
// speedup vs baseline: 1.0141x; 1.0141x over previous
#include <cuda_runtime.h>
#include <math.h>
#include <float.h>

#define DIN   784
#define DH    512
#define DOUT  10
#define BATCH 256

#define BM 64
#define BN 64
#define BK 16
#define KSPLIT 4
#define KCH (DIN / KSPLIT)   // 196

#define KLA_N (49 * 32)
#define KLB_N 49
#define KLC_N 32

// ---------------- device scratch ----------------
__device__ __align__(16) float g_Ws1t[DIN * DH];            // softplus(w_sigma1) [k][h]
__device__ __align__(16) float g_pmu[KSPLIT * BATCH * DH];  // split-K partials mu1
__device__ __align__(16) float g_pq [KSPLIT * BATCH * DH];  // split-K partials quad1
__device__ __align__(16) float g_Ws2[DOUT * DH];            // softplus(w_sigma2) [o][h]
__device__ __align__(16) float g_w2t[DOUT * DH];            // w_mu2 transposed [o][h]
__device__ float g_spb1[DH];
__device__ float g_spb2[DOUT];
__device__ float g_klpartA[KLA_N];
__device__ float g_klpartB[KLB_N];
__device__ float g_klpartC[KLC_N];

// ---------------- softplus: fast poly for x < -1, exact fallback ----------------
__device__ __forceinline__ float sp_pair(float x, float& lsp) {
    if (x < -1.0f) {
        float u = __expf(x);
        float P = 1.0f + u * (-0.5f + u * (0.33333334f + u * (-0.25f +
                  u * (0.2f + u * (-0.16666667f + u * 0.14285715f)))));
        float d = P - 1.0f;
        float lp = d * (1.0f + d * (-0.5f + d * (0.33333334f + d * (-0.25f))));
        lsp = x + lp;
        return u * P;
    } else {
        float sp = logf(1.0f + expf(x));
        lsp = logf(sp);
        return sp;
    }
}
__device__ __forceinline__ float sp_only(float x) {
    if (x < -1.0f) {
        float u = __expf(x);
        float P = 1.0f + u * (-0.5f + u * (0.33333334f + u * (-0.25f +
                  u * (0.2f + u * (-0.16666667f + u * 0.14285715f)))));
        return u * P;
    }
    return logf(1.0f + expf(x));
}

// ---------------- KPREP: softplus transpose + layer-2 prep + KL partials ----------------
// grid (49, 33), block 256. y<32: 16x16 transpose tiles of w_sigma1. y==32: layer-2 prep.
__global__ __launch_bounds__(256) void kprep(const float* __restrict__ w_sigma1,
                                             const float* __restrict__ b_sigma1,
                                             const float* __restrict__ w_mu2,
                                             const float* __restrict__ w_sigma2,
                                             const float* __restrict__ b_sigma2) {
    __shared__ float tile[16][17];
    __shared__ float red[8];
    const int tid = threadIdx.x;
    float acc = 0.f;

    if (blockIdx.y < 32) {
        const int tx = tid & 15, ty = tid >> 4;
        const int k = blockIdx.x * 16 + tx;
        const int h = blockIdx.y * 16 + ty;
        float lsp;
        float sp = sp_pair(w_sigma1[h * DIN + k], lsp);
        tile[ty][tx] = sp;
        acc = sp - lsp;

        #pragma unroll
        for (int s = 16; s; s >>= 1) acc += __shfl_xor_sync(0xffffffffu, acc, s);
        if ((tid & 31) == 0) red[tid >> 5] = acc;
        __syncthreads();
        g_Ws1t[(blockIdx.x * 16 + ty) * DH + blockIdx.y * 16 + tx] = tile[tx][ty];
        if (tid == 0) {
            float t = 0.f;
            #pragma unroll
            for (int w = 0; w < 8; w++) t += red[w];
            g_klpartA[blockIdx.y * 49 + blockIdx.x] = t;
        }
    } else {
        const int T = 49 * 256;
        const int gtid = blockIdx.x * 256 + tid;
        for (int i = gtid; i < DOUT * DH; i += T) {
            float lsp;
            float sp = sp_pair(w_sigma2[i], lsp);
            g_Ws2[i] = sp;
            acc += sp - lsp;
            float v = w_mu2[i];                 // same element count, reuse loop
            acc += v * v;
            g_w2t[(i % DOUT) * DH + (i / DOUT)] = v;
        }
        if (gtid < DH)   g_spb1[gtid] = sp_only(b_sigma1[gtid]);
        if (gtid < DOUT) g_spb2[gtid] = sp_only(b_sigma2[gtid]);

        #pragma unroll
        for (int s = 16; s; s >>= 1) acc += __shfl_xor_sync(0xffffffffu, acc, s);
        if ((tid & 31) == 0) red[tid >> 5] = acc;
        __syncthreads();
        if (tid == 0) {
            float t = 0.f;
            #pragma unroll
            for (int w = 0; w < 8; w++) t += red[w];
            g_klpartB[blockIdx.x] = t;
        }
    }
}

// ---------------- K1: layer-1 dual GEMM (mu1 + quad1), split-K, scalar FFMA ----------------
__global__ __launch_bounds__(256) void k1_gemm(const float* __restrict__ x,
                                               const float* __restrict__ w_mu1) {
    __shared__ __align__(16) float As [BK][68];   // [k][b]
    __shared__ __align__(16) float B1s[BK][68];   // [k][h]
    __shared__ __align__(16) float B2s[BK][68];   // [k][h]
    __shared__ float red[8];

    const int n0 = blockIdx.x * BN;
    const int b0 = blockIdx.y * BM;
    const int ks = blockIdx.z;
    const int kstart = ks * KCH;
    const int kend   = kstart + KCH;

    const int tid = threadIdx.x;
    const int tx = tid & 15, ty = tid >> 4;   // compute microtile coords
    const int ar = tid >> 2, ac = tid & 3;    // A load coords
    const int bk = tid >> 4, bn = tid & 15;   // B load coords
    const bool do_kl = (blockIdx.y == 0);     // by==0 blocks tile w_mu1 disjointly

    float amu[4][4] = {}, aq[4][4] = {};
    float wsq = 0.f;

    for (int k0 = kstart; k0 < kend; k0 += BK) {
        {   // A tile transpose into [k][b]
            int k = k0 + ac * 4;
            float4 v = make_float4(0.f, 0.f, 0.f, 0.f);
            if (k < kend) v = *(const float4*)&x[(b0 + ar) * DIN + k];
            As[ac * 4 + 0][ar] = v.x;
            As[ac * 4 + 1][ar] = v.y;
            As[ac * 4 + 2][ar] = v.z;
            As[ac * 4 + 3][ar] = v.w;
        }
        {   // B1: w_mu1 [k][h] + KL sum-of-squares
            int k = k0 + bk;
            float4 v = make_float4(0.f, 0.f, 0.f, 0.f);
            if (k < kend) v = *(const float4*)&w_mu1[k * DH + n0 + bn * 4];
            *(float4*)&B1s[bk][bn * 4] = v;
            if (do_kl) wsq += v.x * v.x + v.y * v.y + v.z * v.z + v.w * v.w;
        }
        {   // B2: precomputed softplus [k][h]
            int k = k0 + bk;
            float4 v = make_float4(0.f, 0.f, 0.f, 0.f);
            if (k < kend) v = *(const float4*)&g_Ws1t[k * DH + n0 + bn * 4];
            *(float4*)&B2s[bk][bn * 4] = v;
        }
        __syncthreads();

        #pragma unroll
        for (int kk = 0; kk < BK; kk++) {
            float4 a  = *(const float4*)&As [kk][ty * 4];
            float4 b1 = *(const float4*)&B1s[kk][tx * 4];
            float4 b2 = *(const float4*)&B2s[kk][tx * 4];
            float av[4]  = {a.x, a.y, a.z, a.w};
            float b1v[4] = {b1.x, b1.y, b1.z, b1.w};
            float b2v[4] = {b2.x, b2.y, b2.z, b2.w};
            #pragma unroll
            for (int i = 0; i < 4; i++) {
                float ai = av[i];
                float a2 = ai * ai;
                #pragma unroll
                for (int j = 0; j < 4; j++) {
                    amu[i][j] += ai * b1v[j];
                    aq [i][j] += a2 * b2v[j];
                }
            }
        }
        __syncthreads();
    }

    #pragma unroll
    for (int i = 0; i < 4; i++) {
        int b = b0 + ty * 4 + i;
        float4 m = make_float4(amu[i][0], amu[i][1], amu[i][2], amu[i][3]);
        float4 q = make_float4(aq [i][0], aq [i][1], aq [i][2], aq [i][3]);
        *(float4*)&g_pmu[(ks * BATCH + b) * DH + n0 + tx * 4] = m;
        *(float4*)&g_pq [(ks * BATCH + b) * DH + n0 + tx * 4] = q;
    }

    if (do_kl) {
        #pragma unroll
        for (int s = 16; s; s >>= 1) wsq += __shfl_xor_sync(0xffffffffu, wsq, s);
        if ((tid & 31) == 0) red[tid >> 5] = wsq;
        __syncthreads();
        if (tid == 0) {
            float t = 0.f;
            #pragma unroll
            for (int w = 0; w < 8; w++) t += red[w];
            g_klpartC[blockIdx.x * KSPLIT + ks] = t;
        }
    }
}

// ---------------- s2 recompute from partials (for cross-batch trace gather) ----------------
__device__ __forceinline__ float s2_at(int m, int h, const float* __restrict__ b_mu1) {
    const int S = BATCH * DH;
    int idx = m * DH + h;
    float mu = ((g_pmu[idx] + g_pmu[S + idx]) + g_pmu[2 * S + idx]) + g_pmu[3 * S + idx]
               + b_mu1[h];
    if (mu <= 0.f) return 0.f;
    return ((g_pq[idx] + g_pq[S + idx]) + g_pq[2 * S + idx]) + g_pq[3 * S + idx]
           + g_spb1[h];
}

// ---------------- K2: combine + layer 2 + softmax + sandwich + KL finalize ----------------
// block = 64 threads (2 warps = 2 batches), grid = 128
#define TRI_N 55
__global__ __launch_bounds__(64) void k2_layer2(const float* __restrict__ b_mu1,
                                                const float* __restrict__ b_mu2,
                                                float* __restrict__ out) {
    // per-warp scratch: sig[0..99], t1[100..199], p[200..209], mus[210..219],
    //                   qv[220..229], rr[230..239]
    __shared__ float sh[2][240];
    __shared__ float kred[2];
    const int warp = threadIdx.x >> 5, lane = threadIdx.x & 31;
    const int b = blockIdx.x * 2 + warp;
    float* S = sh[warp];
    const int SZ = BATCH * DH;

    float mid[TRI_N], amu[DOUT], aq[DOUT];
    #pragma unroll
    for (int e = 0; e < TRI_N; e++) mid[e] = 0.f;
    #pragma unroll
    for (int o = 0; o < DOUT; o++) { amu[o] = 0.f; aq[o] = 0.f; }

    #pragma unroll 4
    for (int t = 0; t < DH / 32; t++) {
        int h = t * 32 + lane;
        int idx = b * DH + h;
        // inline split-K combine + bias + ReLU
        float mu = ((g_pmu[idx] + g_pmu[SZ + idx]) + g_pmu[2 * SZ + idx]) + g_pmu[3 * SZ + idx]
                   + __ldg(b_mu1 + h);
        bool gate = (mu > 0.f);
        float m = gate ? mu : 0.f;
        float s = gate ? (((g_pq[idx] + g_pq[SZ + idx]) + g_pq[2 * SZ + idx]) + g_pq[3 * SZ + idx]
                          + g_spb1[h]) : 0.f;
        float mm = m * m;
        float w[DOUT], sw[DOUT];
        #pragma unroll
        for (int o = 0; o < DOUT; o++) w[o] = __ldg(&g_w2t[o * DH + h]);
        #pragma unroll
        for (int o = 0; o < DOUT; o++) {
            amu[o] += w[o] * m;
            aq [o] += __ldg(&g_Ws2[o * DH + h]) * mm;
            sw [o]  = s * w[o];
        }
        int e = 0;
        #pragma unroll
        for (int o = 0; o < DOUT; o++)
            #pragma unroll
            for (int p = o; p < DOUT; p++)
                mid[e++] += w[o] * sw[p];
    }

    // butterfly reduce all 75 accumulators across the warp
    #pragma unroll
    for (int s = 16; s; s >>= 1) {
        #pragma unroll
        for (int e = 0; e < TRI_N; e++) mid[e] += __shfl_xor_sync(0xffffffffu, mid[e], s);
        #pragma unroll
        for (int o = 0; o < DOUT; o++) {
            amu[o] += __shfl_xor_sync(0xffffffffu, amu[o], s);
            aq [o] += __shfl_xor_sync(0xffffffffu, aq [o], s);
        }
    }

    // assemble sigma3 into shared
    {
        int e = 0;
        #pragma unroll
        for (int o = 0; o < DOUT; o++) {
            #pragma unroll
            for (int p = o; p < DOUT; p++) {
                if (lane == (e & 31)) {
                    float v = mid[e];
                    if (o == p) {
                        // faithful replication of reference's flattened-view trace term
                        int n  = DOUT * b + o;
                        int qn = n >> 8;
                        int mn = n & 255;
                        float trf = g_Ws2[qn * DH + 2 * mn]     * s2_at(mn, mn, b_mu1)
                                  + g_Ws2[qn * DH + 2 * mn + 1] * s2_at(mn, 256 + mn, b_mu1);
                        v += trf + aq[o] + g_spb2[o];
                        S[o * DOUT + o] = v;
                        S[210 + o] = amu[o] + __ldg(b_mu2 + o);
                    } else {
                        S[o * DOUT + p] = v;
                        S[p * DOUT + o] = v;
                    }
                }
                e++;
            }
        }
    }
    __syncwarp();

    // softmax over DOUT
    {
        float v = (lane < DOUT) ? S[210 + lane] : -FLT_MAX;
        float mx = v;
        #pragma unroll
        for (int s = 16; s; s >>= 1) mx = fmaxf(mx, __shfl_xor_sync(0xffffffffu, mx, s));
        float e = (lane < DOUT) ? expf(v - mx) : 0.f;
        float sm = e;
        #pragma unroll
        for (int s = 16; s; s >>= 1) sm += __shfl_xor_sync(0xffffffffu, sm, s);
        if (lane < DOUT) {
            float p = e / sm;
            S[200 + lane] = p;
            out[b * DOUT + lane] = p;
        }
    }
    __syncwarp();

    // qv[k] = sum_j p[j] * sig[j][k]
    if (lane < DOUT) {
        float a = 0.f;
        #pragma unroll
        for (int j = 0; j < DOUT; j++) a += S[200 + j] * S[j * DOUT + lane];
        S[220 + lane] = a;
    }
    __syncwarp();

    // t1[i][k] = p[i] * (sig[i][k] - qv[k])
    for (int e = lane; e < DOUT * DOUT; e += 32) {
        int i = e / DOUT, k = e % DOUT;
        S[100 + e] = S[200 + i] * (S[e] - S[220 + k]);
    }
    __syncwarp();

    // rr[i] = sum_k t1[i][k] * p[k]
    if (lane < DOUT) {
        float a = 0.f;
        #pragma unroll
        for (int k = 0; k < DOUT; k++) a += S[100 + lane * DOUT + k] * S[200 + k];
        S[230 + lane] = a;
    }
    __syncwarp();

    // Sigma_out[i][l] = p[l] * (t1[i][l] - rr[i])
    for (int e = lane; e < DOUT * DOUT; e += 32) {
        int i = e / DOUT, l = e % DOUT;
        out[BATCH * DOUT + b * DOUT * DOUT + e] = S[200 + l] * (S[100 + e] - S[230 + i]);
    }

    // KL finalize (block 0 only, both warps)
    if (blockIdx.x == 0) {
        float a = 0.f;
        for (int i = threadIdx.x; i < KLA_N; i += 64) a += g_klpartA[i];
        for (int i = threadIdx.x; i < KLB_N; i += 64) a += g_klpartB[i];
        for (int i = threadIdx.x; i < KLC_N; i += 64) a += g_klpartC[i];
        #pragma unroll
        for (int s = 16; s; s >>= 1) a += __shfl_xor_sync(0xffffffffu, a, s);
        if (lane == 0) kred[warp] = a;
        __syncthreads();
        if (threadIdx.x == 0)
            out[BATCH * DOUT + BATCH * DOUT * DOUT] =
                0.5f * ((kred[0] + kred[1]) - (float)(DH * DIN + DOUT * DH));
    }
}

// ---------------- launch ----------------
extern "C" void kernel_launch(void* const* d_in, const int* in_sizes, int n_in,
                              void* d_out, int out_size) {
    const float* x        = (const float*)d_in[0];
    const float* w_mu1    = (const float*)d_in[1];
    const float* w_sigma1 = (const float*)d_in[2];
    const float* b_mu1    = (const float*)d_in[3];
    const float* b_sigma1 = (const float*)d_in[4];
    const float* w_mu2    = (const float*)d_in[5];
    const float* w_sigma2 = (const float*)d_in[6];
    const float* b_mu2    = (const float*)d_in[7];
    const float* b_sigma2 = (const float*)d_in[8];
    float* out = (float*)d_out;

    dim3 gp(49, 33);
    kprep<<<gp, 256>>>(w_sigma1, b_sigma1, w_mu2, w_sigma2, b_sigma2);
    dim3 g1(DH / BN, BATCH / BM, KSPLIT);
    k1_gemm<<<g1, 256>>>(x, w_mu1);
    k2_layer2<<<BATCH / 2, 64>>>(b_mu1, b_mu2, out);
}